// round 16
// baseline (speedup 1.0000x reference)
#include <cuda_runtime.h>
#include <cstdint>

// Problem constants (fixed by the reference)
#define NN    4096     // nodes
#define INF_  128      // input features
#define OUTF  32       // output features per head
#define NH    4        // heads
#define NC    128      // NH*OUTF

// Attention tiling
#define ITILE  32                 // i-rows per block (fine quanta for balance)
#define JSPLIT 8                  // j-range splits (additive partial softmax)
#define JCHUNK (NN / JSPLIT)      // 512
#define JSTEP  32                 // j's per round
#define NROUND (JCHUNK / JSTEP)   // 16

#define LOG2E 1.4426950408889634f
#define WXS_STRIDE 136            // 128 + 8 pad (uint32 units); 544 B (16B-aligned)

// ---------------- scratch (device globals; no allocation allowed) ----------------
// Wx stored ONLY as bf16 j-pair packs: g_WxP[j2*NC + c] = bf16x2(Wx[2j2][c], Wx[2j2+1][c])
__device__ __align__(16) uint32_t g_WxP[(NN / 2) * NC];  // 1 MB
__device__ __align__(16) float g_esA[NN * NH];           // e^{es}
__device__ __align__(16) float g_esC[NN * NH];           // e^{0.2 es}
__device__ __align__(16) float g_edB[NN * NH];           // e^{ed}
__device__ __align__(16) float g_edD[NN * NH];           // e^{0.2 ed}
__device__ __align__(16) float g_nump[JSPLIT][NN * NC];  // 16 MB partial numerators
__device__ __align__(16) float g_Zp[JSPLIT][NN * NH];    // partial denominators

// ---------------- helpers ----------------
__device__ __forceinline__ float ex2f(float x) {
    float r;
    asm("ex2.approx.f32 %0, %1;" : "=f"(r) : "f"(x));
    return r;
}
__device__ __forceinline__ uint32_t smem_u32(const void* p) {
    uint32_t a;
    asm("{ .reg .u64 t; cvta.to.shared.u64 t, %1; cvt.u32.u64 %0, t; }"
        : "=r"(a) : "l"(p));
    return a;
}
// pack two f32 -> bf16x2 (lo = first k element, hi = second)
__device__ __forceinline__ uint32_t pack_bf16(float lo, float hi) {
    uint32_t r;
    asm("cvt.rn.bf16x2.f32 %0, %1, %2;" : "=r"(r) : "f"(hi), "f"(lo));
    return r;
}
// d = (c >= 0) ? a : b   (int condition — NaN-safe mask select)
__device__ __forceinline__ float slct_i(float a, float b, int c) {
    float d;
    asm("slct.f32.s32 %0, %1, %2, %3;" : "=f"(d) : "f"(a), "f"(b), "r"(c));
    return d;
}
// masked P via max form: exp(leaky(s)) = max(e^s, e^{0.2s}) = max(A*B, C*D)
__device__ __forceinline__ float pmask(float A, float B, float C, float D,
                                       uint32_t aw, int sh) {
    float p = fmaxf(A * B, C * D);
    int r = (int)(aw << sh);                    // mask bit -> sign position
    return slct_i(0.0f, p, r);                  // bit=1 -> p, bit=0 -> 0
}
// bf16x2 halves as floats (for consistent Z accumulation)
__device__ __forceinline__ float bflo(uint32_t pk) {
    return __uint_as_float(pk << 16);
}
__device__ __forceinline__ float bfhi(uint32_t pk) {
    return __uint_as_float(pk & 0xFFFF0000u);
}
// m16n8k16 bf16 HMMA (sm_80+ baseline PTX)
__device__ __forceinline__ void mma16(float* d, uint32_t a0, uint32_t a1,
                                      uint32_t a2, uint32_t a3,
                                      uint32_t b0, uint32_t b1) {
    asm volatile(
        "mma.sync.aligned.m16n8k16.row.col.f32.bf16.bf16.f32 "
        "{%0,%1,%2,%3}, {%4,%5,%6,%7}, {%8,%9}, {%0,%1,%2,%3};"
        : "+f"(d[0]), "+f"(d[1]), "+f"(d[2]), "+f"(d[3])
        : "r"(a0), "r"(a1), "r"(a2), "r"(a3), "r"(b0), "r"(b1));
}
__device__ __forceinline__ int ldcs_i(const int* p) {
    int v;
    asm volatile("ld.global.cs.s32 %0, [%1];" : "=r"(v) : "l"(p));
    return v;
}
// async 16B copy global->shared (LDGSTS, .cg = L2-sourced)
__device__ __forceinline__ void cp16(uint32_t dst_sm, const void* src) {
    asm volatile("cp.async.cg.shared.global [%0], [%1], 16;"
                 :: "r"(dst_sm), "l"(src) : "memory");
}
__device__ __forceinline__ void cp_commit() {
    asm volatile("cp.async.commit_group;" ::: "memory");
}
__device__ __forceinline__ void cp_wait0() {
    asm volatile("cp.async.wait_group 0;" ::: "memory");
}

// =====================================================================
// K1: Wx = x @ W, split by column-half for occupancy.
// Grid (2, 128): blockIdx.x = col-half (64 cols = 2 heads),
// blockIdx.y = 32-row tile. 256 threads; W slice 32 KB + x 16 KB = 48 KB.
// Thread (cg=t&15, rg=t>>4) owns 2 rows x 4 cols. Epilogue packs WxP
// pairs (thread owns exactly rows 2rg, 2rg+1) and reduces es/ed for the
// block's two heads.
// =====================================================================
__global__ __launch_bounds__(256) void k_gemm(const float* __restrict__ x,
                                              const float* __restrict__ W,
                                              const float* __restrict__ a) {
    extern __shared__ __align__(16) float sm[];
    float* Ws = sm;            // 128 x 64 floats = 32 KB
    float* xs = sm + 8192;     // 32 x 128 floats = 16 KB
    const int t = threadIdx.x;
    const int ch = blockIdx.x;            // column half (heads 2ch, 2ch+1)
    const int rowbase = blockIdx.y * 32;
    const int colbase = ch * 64;

    // stage W slice: 2048 float4, 8 per thread
    #pragma unroll
    for (int p = 0; p < 8; p++) {
        int idx = t + 256 * p;
        int kr = idx >> 4, c4 = (idx & 15) << 2;
        *(float4*)&Ws[kr * 64 + c4] =
            *(const float4*)&W[(size_t)kr * NC + colbase + c4];
    }
    // stage x tile: 1024 float4, 4 per thread
    #pragma unroll
    for (int p = 0; p < 4; p++) {
        int idx = t + 256 * p;
        int r = idx >> 5, c4 = (idx & 31) << 2;
        *(float4*)&xs[r * 128 + c4] =
            *(const float4*)&x[(size_t)(rowbase + r) * INF_ + c4];
    }
    __syncthreads();

    const int cg = t & 15;
    const int rg = t >> 4;     // 0..15, rows rg*2, rg*2+1
    const int c0 = cg << 2;

    float acc[2][4];
    #pragma unroll
    for (int i = 0; i < 2; i++)
        #pragma unroll
        for (int j = 0; j < 4; j++) acc[i][j] = 0.f;

    #pragma unroll 8
    for (int k = 0; k < INF_; k++) {
        float4 w4 = *(const float4*)&Ws[k * 64 + c0];
        #pragma unroll
        for (int rr = 0; rr < 2; rr++) {
            float xv = xs[(rg * 2 + rr) * 128 + k];
            acc[rr][0] += xv * w4.x;
            acc[rr][1] += xv * w4.y;
            acc[rr][2] += xv * w4.z;
            acc[rr][3] += xv * w4.w;
        }
    }

    // ---- pack row-pair to bf16x2: thread owns pair j2 = rowbase/2 + rg ----
    {
        int j2 = (rowbase >> 1) + rg;
        uint4 pk;
        pk.x = pack_bf16(acc[0][0], acc[1][0]);
        pk.y = pack_bf16(acc[0][1], acc[1][1]);
        pk.z = pack_bf16(acc[0][2], acc[1][2]);
        pk.w = pack_bf16(acc[0][3], acc[1][3]);
        *(uint4*)&g_WxP[(size_t)j2 * NC + colbase + c0] = pk;
    }

    // ---- es/ed for the block's two heads ----
    const int h = ch * 2 + (cg >> 3);          // global head
    const int fbase = c0 & 31;
    #pragma unroll
    for (int rr = 0; rr < 2; rr++) {
        int row = rowbase + rg * 2 + rr;
        float es = 0.f, ed = 0.f;
        #pragma unroll
        for (int q = 0; q < 4; q++) {
            float av = __ldg(&a[h * (2 * OUTF) + fbase + q]);
            float bv = __ldg(&a[h * (2 * OUTF) + OUTF + fbase + q]);
            es += acc[rr][q] * av;
            ed += acc[rr][q] * bv;
        }
        es += __shfl_xor_sync(0xffffffffu, es, 1);
        es += __shfl_xor_sync(0xffffffffu, es, 2);
        es += __shfl_xor_sync(0xffffffffu, es, 4);
        ed += __shfl_xor_sync(0xffffffffu, ed, 1);
        ed += __shfl_xor_sync(0xffffffffu, ed, 2);
        ed += __shfl_xor_sync(0xffffffffu, ed, 4);
        if ((cg & 7) == 0) {
            g_esA[row * NH + h] = ex2f(es * LOG2E);
            g_esC[row * NH + h] = ex2f(0.2f * es * LOG2E);
            g_edB[row * NH + h] = ex2f(ed * LOG2E);
            g_edD[row * NH + h] = ex2f(0.2f * ed * LOG2E);
        }
    }
}

// =====================================================================
// K2: bf16 m16n8k16 HMMA attention aggregation, exp-factorized P.
// Grid (8, 128) = 1024 blocks. Block 128 = 4 warps; warp == head;
// 32i x 32f per warp over K=512 (2 m-tiles x 4 n-tiles).
// Wx restaging now via cp.async.cg issued BEFORE the MMA loop and
// waited after it — L2 reads fully overlap HMMA.
// =====================================================================
__global__ __launch_bounds__(128, 4) void k_attn(const int* __restrict__ adj) {
    __shared__ __align__(16) uint32_t WxS[2][16 * WXS_STRIDE];  // 17408 B
    __shared__ __align__(16) float edB[NH][JCHUNK];             //  8192 B
    __shared__ __align__(16) float edD[NH][JCHUNK];             //  8192 B
    __shared__ uint32_t adjW[2][ITILE];                         //   256 B

    const int t = threadIdx.x;
    const int w = t >> 5, lane = t & 31;
    const int g = lane >> 2, tig = lane & 3;
    const int h = w;                    // warp == head
    const int ibase = blockIdx.y * ITILE;
    const int jc = blockIdx.x;
    const int jbase = jc * JCHUNK;
    const int jb2 = jbase >> 1;         // pair-index base

    // cp.async staging slots for this thread (4 x 16B per round)
    const int st_j2 = t >> 5;           // via idx = t + 128p: j2 = idx>>5
    const int st_c4 = (t & 31) << 2;
    uint32_t wxs_sm[2];
    wxs_sm[0] = smem_u32(&WxS[0][0]);
    wxs_sm[1] = smem_u32(&WxS[1][0]);

    // stage ed-side exponentials, transposed to head-major
    for (int idx = t; idx < JCHUNK; idx += 128) {
        float4 b4 = *(const float4*)&g_edB[(size_t)(jbase + idx) * NH];
        edB[0][idx] = b4.x; edB[1][idx] = b4.y;
        edB[2][idx] = b4.z; edB[3][idx] = b4.w;
        float4 d4 = *(const float4*)&g_edD[(size_t)(jbase + idx) * NH];
        edD[0][idx] = d4.x; edD[1][idx] = d4.y;
        edD[2][idx] = d4.z; edD[3][idx] = d4.w;
    }

    // es-side exponentials for my 4 rows
    float eA[2][2], eC[2][2];
    #pragma unroll
    for (int mt = 0; mt < 2; mt++) {
        eA[mt][0] = g_esA[(size_t)(ibase + mt * 16 + g) * NH + h];
        eA[mt][1] = g_esA[(size_t)(ibase + mt * 16 + g + 8) * NH + h];
        eC[mt][0] = g_esC[(size_t)(ibase + mt * 16 + g) * NH + h];
        eC[mt][1] = g_esC[(size_t)(ibase + mt * 16 + g + 8) * NH + h];
    }

    float acc[2][4][4];
    #pragma unroll
    for (int mt = 0; mt < 2; mt++)
        #pragma unroll
        for (int nt = 0; nt < 4; nt++)
            #pragma unroll
            for (int q = 0; q < 4; q++) acc[mt][nt][q] = 0.f;
    float z[2][2];
    #pragma unroll
    for (int mt = 0; mt < 2; mt++) { z[mt][0] = 0.f; z[mt][1] = 0.f; }

    // adj staging rows for this warp: ibase + w*8 .. +7 (lane = j)
    const int* arow = adj + (size_t)(ibase + w * 8) * NN + jbase;

    // ---------------- prologue: stage round 0 ----------------
    {
        int av[8];
        #pragma unroll
        for (int q = 0; q < 8; q++) av[q] = ldcs_i(&arow[(size_t)q * NN + lane]);
        #pragma unroll
        for (int q = 0; q < 8; q++) {
            uint32_t m = __ballot_sync(0xffffffffu, av[q] != 0);
            if (lane == 0) adjW[0][w * 8 + q] = m;
        }
        #pragma unroll
        for (int p = 0; p < 4; p++) {
            int j2 = st_j2 + 4 * p;
            cp16(wxs_sm[0] + (uint32_t)(j2 * WXS_STRIDE + st_c4) * 4,
                 &g_WxP[(size_t)(jb2 + j2) * NC + st_c4]);
        }
        cp_commit();
        cp_wait0();
    }
    __syncthreads();

    // ---------------- main loop ----------------
    for (int r = 0; r < NROUND; r++) {
        const int b = r & 1;

        // EARLY: async-stage next round's Wx + prefetch next adj into regs
        int avn[8];
        if (r < NROUND - 1) {
            #pragma unroll
            for (int p = 0; p < 4; p++) {
                int j2 = st_j2 + 4 * p;
                cp16(wxs_sm[b ^ 1] + (uint32_t)(j2 * WXS_STRIDE + st_c4) * 4,
                     &g_WxP[(size_t)(jb2 + (r + 1) * 16 + j2) * NC + st_c4]);
            }
            cp_commit();
            #pragma unroll
            for (int q = 0; q < 8; q++)
                avn[q] = ldcs_i(&arow[(size_t)q * NN + (r + 1) * JSTEP + lane]);
        }

        // my 4 mask words for this round
        uint32_t aw[2][2];
        #pragma unroll
        for (int mt = 0; mt < 2; mt++) {
            aw[mt][0] = adjW[b][mt * 16 + g];
            aw[mt][1] = adjW[b][mt * 16 + g + 8];
        }

        #pragma unroll
        for (int ks = 0; ks < 2; ks++) {     // two K=16 steps
            const int jq = ks * 8;           // j-pair base within round
            // B fragments (4 n-tiles), conflict-free (banks 8*tig+g)
            uint32_t b0[4], b1[4];
            #pragma unroll
            for (int nt = 0; nt < 4; nt++) {
                b0[nt] = WxS[b][(jq + tig) * WXS_STRIDE + h * OUTF + nt * 8 + g];
                b1[nt] = WxS[b][(jq + tig + 4) * WXS_STRIDE + h * OUTF + nt * 8 + g];
            }
            // ed-side exponential pairs (LDS.64 broadcast within quads)
            const int kb = r * JSTEP + ks * 16 + 2 * tig;
            float2 B0 = *(const float2*)&edB[h][kb];
            float2 B1 = *(const float2*)&edB[h][kb + 8];
            float2 D0 = *(const float2*)&edD[h][kb];
            float2 D1 = *(const float2*)&edD[h][kb + 8];
            const int sh0 = 31 - (ks * 16 + 2 * tig);   // bit j0 -> sign

            #pragma unroll
            for (int mt = 0; mt < 2; mt++) {
                // row g
                float p00 = pmask(eA[mt][0], B0.x, eC[mt][0], D0.x, aw[mt][0], sh0);
                float p01 = pmask(eA[mt][0], B0.y, eC[mt][0], D0.y, aw[mt][0], sh0 - 1);
                float p02 = pmask(eA[mt][0], B1.x, eC[mt][0], D1.x, aw[mt][0], sh0 - 8);
                float p03 = pmask(eA[mt][0], B1.y, eC[mt][0], D1.y, aw[mt][0], sh0 - 9);
                // row g+8
                float p10 = pmask(eA[mt][1], B0.x, eC[mt][1], D0.x, aw[mt][1], sh0);
                float p11 = pmask(eA[mt][1], B0.y, eC[mt][1], D0.y, aw[mt][1], sh0 - 1);
                float p12 = pmask(eA[mt][1], B1.x, eC[mt][1], D1.x, aw[mt][1], sh0 - 8);
                float p13 = pmask(eA[mt][1], B1.y, eC[mt][1], D1.y, aw[mt][1], sh0 - 9);
                uint32_t a0 = pack_bf16(p00, p01);
                uint32_t a1 = pack_bf16(p10, p11);
                uint32_t a2 = pack_bf16(p02, p03);
                uint32_t a3 = pack_bf16(p12, p13);
                // Z from the bf16-rounded P (consistent with the numerator)
                z[mt][0] += (bflo(a0) + bfhi(a0)) + (bflo(a2) + bfhi(a2));
                z[mt][1] += (bflo(a1) + bfhi(a1)) + (bflo(a3) + bfhi(a3));
                #pragma unroll
                for (int nt = 0; nt < 4; nt++)
                    mma16(acc[mt][nt], a0, a1, a2, a3, b0[nt], b1[nt]);
            }
        }

        // LATE: pack prefetched adj; drain async Wx copies; barrier
        if (r < NROUND - 1) {
            #pragma unroll
            for (int q = 0; q < 8; q++) {
                uint32_t m = __ballot_sync(0xffffffffu, avn[q] != 0);
                if (lane == 0) adjW[b ^ 1][w * 8 + q] = m;
            }
            cp_wait0();
        }
        __syncthreads();
    }

    // ---- epilogue: D fragments -> partial numerators; Z reduce ----
    float* np = g_nump[jc];
    #pragma unroll
    for (int mt = 0; mt < 2; mt++) {
        int r0 = ibase + mt * 16 + g;
        #pragma unroll
        for (int nt = 0; nt < 4; nt++) {
            int c = h * OUTF + nt * 8 + tig * 2;
            *(float2*)&np[(size_t)r0 * NC + c] =
                make_float2(acc[mt][nt][0], acc[mt][nt][1]);
            *(float2*)&np[(size_t)(r0 + 8) * NC + c] =
                make_float2(acc[mt][nt][2], acc[mt][nt][3]);
        }
        float z0 = z[mt][0], z1 = z[mt][1];
        z0 += __shfl_xor_sync(0xffffffffu, z0, 1);
        z0 += __shfl_xor_sync(0xffffffffu, z0, 2);
        z1 += __shfl_xor_sync(0xffffffffu, z1, 1);
        z1 += __shfl_xor_sync(0xffffffffu, z1, 2);
        if (tig == 0) {
            g_Zp[jc][(size_t)r0 * NH + h] = z0;
            g_Zp[jc][(size_t)(r0 + 8) * NH + h] = z1;
        }
    }
}

// =====================================================================
// K3: normalize — out = (sum_s num_s) / (sum_s Z_s).
// =====================================================================
__global__ __launch_bounds__(256) void k_norm(float* __restrict__ out) {
    int g = blockIdx.x * 256 + threadIdx.x;
    int i = g >> 5;
    int c4 = (g & 31) << 2;
    int h = c4 >> 5;
    float4 num = make_float4(0.f, 0.f, 0.f, 0.f);
    float Z = 0.f;
    #pragma unroll
    for (int s = 0; s < JSPLIT; s++) {
        float4 v = *(const float4*)&g_nump[s][(size_t)i * NC + c4];
        num.x += v.x; num.y += v.y; num.z += v.z; num.w += v.w;
        Z += g_Zp[s][i * NH + h];
    }
    float inv = 1.f / Z;
    *(float4*)&out[(size_t)i * NC + c4] =
        make_float4(num.x * inv, num.y * inv, num.z * inv, num.w * inv);
}

// =====================================================================
extern "C" void kernel_launch(void* const* d_in, const int* in_sizes, int n_in,
                              void* d_out, int out_size) {
    const float* x = nullptr;
    const int*   adj = nullptr;
    const float* W = nullptr;
    const float* a = nullptr;
    for (int i = 0; i < n_in; i++) {
        switch (in_sizes[i]) {
            case NN * INF_:       x   = (const float*)d_in[i]; break;
            case NN * NN:         adj = (const int*)d_in[i];   break;
            case INF_ * NC:       W   = (const float*)d_in[i]; break;
            case NH * 2 * OUTF:   a   = (const float*)d_in[i]; break;
            default: break;
        }
    }
    float* out = (float*)d_out;

    // k_gemm: 48 KB dynamic smem (attribute set defensively; graph-safe).
    const int gemm_smem = (8192 + 4096) * (int)sizeof(float);  // 49152
    cudaFuncSetAttribute(k_gemm, cudaFuncAttributeMaxDynamicSharedMemorySize,
                         gemm_smem);

    dim3 g_gemm(2, NN / 32);           // (2, 128)
    k_gemm<<<g_gemm, 256, gemm_smem>>>(x, W, a);
    dim3 g_attn(JSPLIT, NN / ITILE);   // (8, 128)
    k_attn<<<g_attn, 128>>>(adj);
    k_norm<<<(NN * NC / 4) / 256, 256>>>(out);
    (void)out_size;
}

// round 17
// speedup vs baseline: 1.1391x; 1.1391x over previous
#include <cuda_runtime.h>
#include <cstdint>

// Problem constants (fixed by the reference)
#define NN    4096     // nodes
#define INF_  128      // input features
#define OUTF  32       // output features per head
#define NH    4        // heads
#define NC    128      // NH*OUTF

// Attention tiling
#define ITILE  32                 // i-rows per block (fine quanta for balance)
#define JSPLIT 8                  // j-range splits (additive partial softmax)
#define JCHUNK (NN / JSPLIT)      // 512
#define JSTEP  32                 // j's per round
#define NROUND (JCHUNK / JSTEP)   // 16

#define LOG2E 1.4426950408889634f
#define WXS_STRIDE 136            // 128 + 8 pad (uint32 units)

// ---------------- scratch (device globals; no allocation allowed) ----------------
// Wx stored ONLY as bf16 j-pair packs: g_WxP[j2*NC + c] = bf16x2(Wx[2j2][c], Wx[2j2+1][c])
__device__ __align__(16) uint32_t g_WxP[(NN / 2) * NC];  // 1 MB
__device__ __align__(16) float g_esA[NN * NH];           // e^{es}
__device__ __align__(16) float g_esC[NN * NH];           // e^{0.2 es}
__device__ __align__(16) float g_edB[NN * NH];           // e^{ed}
__device__ __align__(16) float g_edD[NN * NH];           // e^{0.2 ed}
__device__ __align__(16) float g_nump[JSPLIT][NN * NC];  // 16 MB partial numerators
__device__ __align__(16) float g_Zp[JSPLIT][NN * NH];    // partial denominators

// ---------------- helpers ----------------
__device__ __forceinline__ float ex2f(float x) {
    float r;
    asm("ex2.approx.f32 %0, %1;" : "=f"(r) : "f"(x));
    return r;
}
// pack two f32 -> bf16x2 (lo = first k element, hi = second)
__device__ __forceinline__ uint32_t pack_bf16(float lo, float hi) {
    uint32_t r;
    asm("cvt.rn.bf16x2.f32 %0, %1, %2;" : "=r"(r) : "f"(hi), "f"(lo));
    return r;
}
// d = (c >= 0) ? a : b   (int condition — NaN-safe mask select)
__device__ __forceinline__ float slct_i(float a, float b, int c) {
    float d;
    asm("slct.f32.s32 %0, %1, %2, %3;" : "=f"(d) : "f"(a), "f"(b), "r"(c));
    return d;
}
// masked P via max form: exp(leaky(s)) = max(e^s, e^{0.2s}) = max(A*B, C*D)
__device__ __forceinline__ float pmask(float A, float B, float C, float D,
                                       uint32_t aw, int sh) {
    float p = fmaxf(A * B, C * D);
    int r = (int)(aw << sh);                    // mask bit -> sign position
    return slct_i(0.0f, p, r);                  // bit=1 -> p, bit=0 -> 0
}
// bf16x2 halves as floats (for consistent Z accumulation)
__device__ __forceinline__ float bflo(uint32_t pk) {
    return __uint_as_float(pk << 16);
}
__device__ __forceinline__ float bfhi(uint32_t pk) {
    return __uint_as_float(pk & 0xFFFF0000u);
}
// m16n8k16 bf16 HMMA (sm_80+ baseline PTX)
__device__ __forceinline__ void mma16(float* d, uint32_t a0, uint32_t a1,
                                      uint32_t a2, uint32_t a3,
                                      uint32_t b0, uint32_t b1) {
    asm volatile(
        "mma.sync.aligned.m16n8k16.row.col.f32.bf16.bf16.f32 "
        "{%0,%1,%2,%3}, {%4,%5,%6,%7}, {%8,%9}, {%0,%1,%2,%3};"
        : "+f"(d[0]), "+f"(d[1]), "+f"(d[2]), "+f"(d[3])
        : "r"(a0), "r"(a1), "r"(a2), "r"(a3), "r"(b0), "r"(b1));
}
__device__ __forceinline__ int ldcs_i(const int* p) {
    int v;
    asm volatile("ld.global.cs.s32 %0, [%1];" : "=r"(v) : "l"(p));
    return v;
}

// =====================================================================
// K1: Wx = x @ W. 256 threads, 32 rows/block (grid 128), 4 rows x 4 cols
// per thread. Full W staged once (64 KB) + x tile (16 KB): 80 KB dynamic
// smem -> opt-in. Epilogue packs Wx row-pairs to bf16x2 (g_WxP) and
// stores per-(node,head) exponentials A,C,B,D.  (R15 version: 10.2us)
// =====================================================================
__global__ __launch_bounds__(256) void k_gemm(const float* __restrict__ x,
                                              const float* __restrict__ W,
                                              const float* __restrict__ a) {
    extern __shared__ __align__(16) float sm[];
    float* Ws = sm;            // 128*128 floats = 64 KB
    float* xs = sm + 16384;    // 32*128  floats = 16 KB
    const int t = threadIdx.x;
    const int rowbase = blockIdx.x * 32;

    #pragma unroll
    for (int p = 0; p < 16; p++) {
        int idx = t + 256 * p;
        int kr = idx >> 5, c4 = (idx & 31) << 2;
        *(float4*)&Ws[kr * 128 + c4] = *(const float4*)&W[(size_t)kr * NC + c4];
    }
    #pragma unroll
    for (int p = 0; p < 4; p++) {
        int idx = t + 256 * p;
        int r = idx >> 5, c4 = (idx & 31) << 2;
        *(float4*)&xs[r * 128 + c4] =
            *(const float4*)&x[(size_t)(rowbase + r) * INF_ + c4];
    }
    __syncthreads();

    const int cg = t & 31;
    const int rg = t >> 5;     // 0..7, rows rg*4..rg*4+3
    const int c0 = cg << 2;

    float acc[4][4];
    #pragma unroll
    for (int i = 0; i < 4; i++)
        #pragma unroll
        for (int j = 0; j < 4; j++) acc[i][j] = 0.f;

    #pragma unroll 4
    for (int k = 0; k < INF_; k++) {
        float4 w4 = *(const float4*)&Ws[k * 128 + c0];
        #pragma unroll
        for (int rr = 0; rr < 4; rr++) {
            float xv = xs[(rg * 4 + rr) * 128 + k];
            acc[rr][0] += xv * w4.x;
            acc[rr][1] += xv * w4.y;
            acc[rr][2] += xv * w4.z;
            acc[rr][3] += xv * w4.w;
        }
    }

    // ---- pack row-pairs to bf16x2 (rows rg*4+{0,1} and rg*4+{2,3}) ----
    {
        int j2base = (rowbase >> 1) + rg * 2;   // global pair index
        #pragma unroll
        for (int pr = 0; pr < 2; pr++) {
            uint4 pk;
            pk.x = pack_bf16(acc[2 * pr][0], acc[2 * pr + 1][0]);
            pk.y = pack_bf16(acc[2 * pr][1], acc[2 * pr + 1][1]);
            pk.z = pack_bf16(acc[2 * pr][2], acc[2 * pr + 1][2]);
            pk.w = pack_bf16(acc[2 * pr][3], acc[2 * pr + 1][3]);
            *(uint4*)&g_WxP[(size_t)(j2base + pr) * NC + c0] = pk;
        }
    }

    const int h = cg >> 3;
    const int fbase = c0 & 31;
    #pragma unroll
    for (int rr = 0; rr < 4; rr++) {
        int row = rowbase + rg * 4 + rr;
        float es = 0.f, ed = 0.f;
        #pragma unroll
        for (int q = 0; q < 4; q++) {
            float av = __ldg(&a[h * (2 * OUTF) + fbase + q]);
            float bv = __ldg(&a[h * (2 * OUTF) + OUTF + fbase + q]);
            es += acc[rr][q] * av;
            ed += acc[rr][q] * bv;
        }
        es += __shfl_xor_sync(0xffffffffu, es, 1);
        es += __shfl_xor_sync(0xffffffffu, es, 2);
        es += __shfl_xor_sync(0xffffffffu, es, 4);
        ed += __shfl_xor_sync(0xffffffffu, ed, 1);
        ed += __shfl_xor_sync(0xffffffffu, ed, 2);
        ed += __shfl_xor_sync(0xffffffffu, ed, 4);
        if ((cg & 7) == 0) {
            g_esA[row * NH + h] = ex2f(es * LOG2E);
            g_esC[row * NH + h] = ex2f(0.2f * es * LOG2E);
            g_edB[row * NH + h] = ex2f(ed * LOG2E);
            g_edD[row * NH + h] = ex2f(0.2f * ed * LOG2E);
        }
    }
}

// =====================================================================
// K2: bf16 m16n8k16 HMMA attention aggregation, exp-factorized P.
// Grid (8, 128) = 1024 blocks. Block 128 = 4 warps; warp == head;
// 32i x 32f per warp over K=512 (2 m-tiles x 4 n-tiles).
// R15 structure; CHANGE: next-round Wx uint4 LDGs hoisted to the round
// top (into registers, alongside the adj prefetch) so their L2 latency
// is covered by the MMA loop; only the STS remains in the LATE section.
// =====================================================================
__global__ __launch_bounds__(128, 4) void k_attn(const int* __restrict__ adj) {
    __shared__ __align__(16) uint32_t WxS[2][16 * WXS_STRIDE];  // 17408 B
    __shared__ __align__(16) float edB[NH][JCHUNK];             //  8192 B
    __shared__ __align__(16) float edD[NH][JCHUNK];             //  8192 B
    __shared__ uint32_t adjW[2][ITILE];                         //   256 B

    const int t = threadIdx.x;
    const int w = t >> 5, lane = t & 31;
    const int g = lane >> 2, tig = lane & 3;
    const int h = w;                    // warp == head
    const int ibase = blockIdx.y * ITILE;
    const int jc = blockIdx.x;
    const int jbase = jc * JCHUNK;
    const int jb2 = jbase >> 1;         // pair-index base

    // Wx staging slots for this thread: j2 = (t>>5) + 4p, c4 = (t&31)*4
    const int st_j2 = t >> 5;
    const int st_c4 = (t & 31) << 2;

    // stage ed-side exponentials, transposed to head-major
    for (int idx = t; idx < JCHUNK; idx += 128) {
        float4 b4 = *(const float4*)&g_edB[(size_t)(jbase + idx) * NH];
        edB[0][idx] = b4.x; edB[1][idx] = b4.y;
        edB[2][idx] = b4.z; edB[3][idx] = b4.w;
        float4 d4 = *(const float4*)&g_edD[(size_t)(jbase + idx) * NH];
        edD[0][idx] = d4.x; edD[1][idx] = d4.y;
        edD[2][idx] = d4.z; edD[3][idx] = d4.w;
    }

    // es-side exponentials for my 4 rows
    float eA[2][2], eC[2][2];
    #pragma unroll
    for (int mt = 0; mt < 2; mt++) {
        eA[mt][0] = g_esA[(size_t)(ibase + mt * 16 + g) * NH + h];
        eA[mt][1] = g_esA[(size_t)(ibase + mt * 16 + g + 8) * NH + h];
        eC[mt][0] = g_esC[(size_t)(ibase + mt * 16 + g) * NH + h];
        eC[mt][1] = g_esC[(size_t)(ibase + mt * 16 + g + 8) * NH + h];
    }

    float acc[2][4][4];
    #pragma unroll
    for (int mt = 0; mt < 2; mt++)
        #pragma unroll
        for (int nt = 0; nt < 4; nt++)
            #pragma unroll
            for (int q = 0; q < 4; q++) acc[mt][nt][q] = 0.f;
    float z[2][2];
    #pragma unroll
    for (int mt = 0; mt < 2; mt++) { z[mt][0] = 0.f; z[mt][1] = 0.f; }

    // adj staging rows for this warp: ibase + w*8 .. +7 (lane = j)
    const int* arow = adj + (size_t)(ibase + w * 8) * NN + jbase;

    // ---------------- prologue: stage round 0 ----------------
    {
        int av[8];
        #pragma unroll
        for (int q = 0; q < 8; q++) av[q] = ldcs_i(&arow[(size_t)q * NN + lane]);
        #pragma unroll
        for (int q = 0; q < 8; q++) {
            uint32_t m = __ballot_sync(0xffffffffu, av[q] != 0);
            if (lane == 0) adjW[0][w * 8 + q] = m;
        }
        #pragma unroll
        for (int p = 0; p < 4; p++) {
            int j2 = st_j2 + 4 * p;
            uint4 v = *(const uint4*)&g_WxP[(size_t)(jb2 + j2) * NC + st_c4];
            *(uint4*)&WxS[0][j2 * WXS_STRIDE + st_c4] = v;
        }
    }
    __syncthreads();

    // ---------------- main loop ----------------
    for (int r = 0; r < NROUND; r++) {
        const int b = r & 1;

        // EARLY: prefetch next round's adj AND Wx into registers
        // (latency covered by the MMA loop below)
        int avn[8];
        uint4 wxn[4];
        if (r < NROUND - 1) {
            #pragma unroll
            for (int p = 0; p < 4; p++) {
                int j2 = st_j2 + 4 * p;
                wxn[p] = *(const uint4*)
                    &g_WxP[(size_t)(jb2 + (r + 1) * 16 + j2) * NC + st_c4];
            }
            #pragma unroll
            for (int q = 0; q < 8; q++)
                avn[q] = ldcs_i(&arow[(size_t)q * NN + (r + 1) * JSTEP + lane]);
        }

        // my 4 mask words for this round
        uint32_t aw[2][2];
        #pragma unroll
        for (int mt = 0; mt < 2; mt++) {
            aw[mt][0] = adjW[b][mt * 16 + g];
            aw[mt][1] = adjW[b][mt * 16 + g + 8];
        }

        #pragma unroll
        for (int ks = 0; ks < 2; ks++) {     // two K=16 steps
            const int jq = ks * 8;           // j-pair base within round
            // B fragments (4 n-tiles), conflict-free (banks 8*tig+g)
            uint32_t b0[4], b1[4];
            #pragma unroll
            for (int nt = 0; nt < 4; nt++) {
                b0[nt] = WxS[b][(jq + tig) * WXS_STRIDE + h * OUTF + nt * 8 + g];
                b1[nt] = WxS[b][(jq + tig + 4) * WXS_STRIDE + h * OUTF + nt * 8 + g];
            }
            // ed-side exponential pairs (LDS.64 broadcast within quads)
            const int kb = r * JSTEP + ks * 16 + 2 * tig;
            float2 B0 = *(const float2*)&edB[h][kb];
            float2 B1 = *(const float2*)&edB[h][kb + 8];
            float2 D0 = *(const float2*)&edD[h][kb];
            float2 D1 = *(const float2*)&edD[h][kb + 8];
            const int sh0 = 31 - (ks * 16 + 2 * tig);   // bit j0 -> sign

            #pragma unroll
            for (int mt = 0; mt < 2; mt++) {
                // row g
                float p00 = pmask(eA[mt][0], B0.x, eC[mt][0], D0.x, aw[mt][0], sh0);
                float p01 = pmask(eA[mt][0], B0.y, eC[mt][0], D0.y, aw[mt][0], sh0 - 1);
                float p02 = pmask(eA[mt][0], B1.x, eC[mt][0], D1.x, aw[mt][0], sh0 - 8);
                float p03 = pmask(eA[mt][0], B1.y, eC[mt][0], D1.y, aw[mt][0], sh0 - 9);
                // row g+8
                float p10 = pmask(eA[mt][1], B0.x, eC[mt][1], D0.x, aw[mt][1], sh0);
                float p11 = pmask(eA[mt][1], B0.y, eC[mt][1], D0.y, aw[mt][1], sh0 - 1);
                float p12 = pmask(eA[mt][1], B1.x, eC[mt][1], D1.x, aw[mt][1], sh0 - 8);
                float p13 = pmask(eA[mt][1], B1.y, eC[mt][1], D1.y, aw[mt][1], sh0 - 9);
                uint32_t a0 = pack_bf16(p00, p01);
                uint32_t a1 = pack_bf16(p10, p11);
                uint32_t a2 = pack_bf16(p02, p03);
                uint32_t a3 = pack_bf16(p12, p13);
                // Z from the bf16-rounded P (consistent with the numerator)
                z[mt][0] += (bflo(a0) + bfhi(a0)) + (bflo(a2) + bfhi(a2));
                z[mt][1] += (bflo(a1) + bfhi(a1)) + (bflo(a3) + bfhi(a3));
                #pragma unroll
                for (int nt = 0; nt < 4; nt++)
                    mma16(acc[mt][nt], a0, a1, a2, a3, b0[nt], b1[nt]);
            }
        }

        // LATE: pack prefetched adj + store prefetched Wx into buffer b^1
        if (r < NROUND - 1) {
            #pragma unroll
            for (int q = 0; q < 8; q++) {
                uint32_t m = __ballot_sync(0xffffffffu, avn[q] != 0);
                if (lane == 0) adjW[b ^ 1][w * 8 + q] = m;
            }
            #pragma unroll
            for (int p = 0; p < 4; p++) {
                int j2 = st_j2 + 4 * p;
                *(uint4*)&WxS[b ^ 1][j2 * WXS_STRIDE + st_c4] = wxn[p];
            }
        }
        __syncthreads();
    }

    // ---- epilogue: D fragments -> partial numerators; Z reduce ----
    float* np = g_nump[jc];
    #pragma unroll
    for (int mt = 0; mt < 2; mt++) {
        int r0 = ibase + mt * 16 + g;
        #pragma unroll
        for (int nt = 0; nt < 4; nt++) {
            int c = h * OUTF + nt * 8 + tig * 2;
            *(float2*)&np[(size_t)r0 * NC + c] =
                make_float2(acc[mt][nt][0], acc[mt][nt][1]);
            *(float2*)&np[(size_t)(r0 + 8) * NC + c] =
                make_float2(acc[mt][nt][2], acc[mt][nt][3]);
        }
        float z0 = z[mt][0], z1 = z[mt][1];
        z0 += __shfl_xor_sync(0xffffffffu, z0, 1);
        z0 += __shfl_xor_sync(0xffffffffu, z0, 2);
        z1 += __shfl_xor_sync(0xffffffffu, z1, 1);
        z1 += __shfl_xor_sync(0xffffffffu, z1, 2);
        if (tig == 0) {
            g_Zp[jc][(size_t)r0 * NH + h] = z0;
            g_Zp[jc][(size_t)(r0 + 8) * NH + h] = z1;
        }
    }
}

// =====================================================================
// K3: normalize — out = (sum_s num_s) / (sum_s Z_s).
// =====================================================================
__global__ __launch_bounds__(256) void k_norm(float* __restrict__ out) {
    int g = blockIdx.x * 256 + threadIdx.x;
    int i = g >> 5;
    int c4 = (g & 31) << 2;
    int h = c4 >> 5;
    float4 num = make_float4(0.f, 0.f, 0.f, 0.f);
    float Z = 0.f;
    #pragma unroll
    for (int s = 0; s < JSPLIT; s++) {
        float4 v = *(const float4*)&g_nump[s][(size_t)i * NC + c4];
        num.x += v.x; num.y += v.y; num.z += v.z; num.w += v.w;
        Z += g_Zp[s][i * NH + h];
    }
    float inv = 1.f / Z;
    *(float4*)&out[(size_t)i * NC + c4] =
        make_float4(num.x * inv, num.y * inv, num.z * inv, num.w * inv);
}

// =====================================================================
extern "C" void kernel_launch(void* const* d_in, const int* in_sizes, int n_in,
                              void* d_out, int out_size) {
    const float* x = nullptr;
    const int*   adj = nullptr;
    const float* W = nullptr;
    const float* a = nullptr;
    for (int i = 0; i < n_in; i++) {
        switch (in_sizes[i]) {
            case NN * INF_:       x   = (const float*)d_in[i]; break;
            case NN * NN:         adj = (const int*)d_in[i];   break;
            case INF_ * NC:       W   = (const float*)d_in[i]; break;
            case NH * 2 * OUTF:   a   = (const float*)d_in[i]; break;
            default: break;
        }
    }
    float* out = (float*)d_out;

    // k_gemm uses 80 KB dynamic smem: opt-in (host attribute; graph-safe).
    const int gemm_smem = (16384 + 4096) * (int)sizeof(float);  // 81920
    cudaFuncSetAttribute(k_gemm, cudaFuncAttributeMaxDynamicSharedMemorySize,
                         gemm_smem);

    k_gemm<<<NN / 32, 256, gemm_smem>>>(x, W, a);
    dim3 g_attn(JSPLIT, NN / ITILE);   // (8, 128)
    k_attn<<<g_attn, 128>>>(adj);
    k_norm<<<(NN * NC / 4) / 256, 256>>>(out);
    (void)out_size;
}